// round 1
// baseline (speedup 1.0000x reference)
#include <cuda_runtime.h>
#include <cuda_bf16.h>

// Problem constants (fixed shapes per reference)
#define N_SRC 50000
#define N_DST 50000
#define NE    800000
#define FIN   128     // F_IN, also H*D
#define NEG_SLOPE 0.2f

// ---------------------------------------------------------------------------
// Scratch (static __device__ arrays; no runtime allocation allowed)
// ---------------------------------------------------------------------------
__device__ float g_m[(size_t)NE * FIN];     // per-edge messages m = ps[src] + edge@We  (409.6 MB)
__device__ float g_ps[(size_t)N_SRC * FIN]; // src_feat @ W_src[:128]
__device__ float g_nh[(size_t)N_DST * FIN]; // dst_feat @ W_dst
__device__ int   g_deg[N_DST];
__device__ int   g_off[N_DST + 1];
__device__ int   g_cursor[N_DST];
__device__ int   g_edges[NE];               // edge ids grouped by dst (CSR)

// ---------------------------------------------------------------------------
// CSR build
// ---------------------------------------------------------------------------
__global__ void zero_deg_kernel() {
    int i = blockIdx.x * blockDim.x + threadIdx.x;
    if (i < N_DST) g_deg[i] = 0;
}

__global__ void hist_kernel(const int* __restrict__ dst_idx) {
    int e = blockIdx.x * blockDim.x + threadIdx.x;
    if (e < NE) atomicAdd(&g_deg[dst_idx[e]], 1);
}

// Single-block Hillis-Steele chunked exclusive scan over g_deg -> g_off, g_cursor
__global__ void scan_kernel() {
    __shared__ int sh[1024];
    const int t = threadIdx.x;
    int carry = 0;
    for (int base = 0; base < N_DST; base += 1024) {
        int i = base + t;
        int v = (i < N_DST) ? g_deg[i] : 0;
        sh[t] = v;
        __syncthreads();
        #pragma unroll
        for (int off = 1; off < 1024; off <<= 1) {
            int tmp = (t >= off) ? sh[t - off] : 0;
            __syncthreads();
            sh[t] += tmp;
            __syncthreads();
        }
        int incl  = sh[t];
        int total = sh[1023];
        __syncthreads();   // everyone done reading sh before next chunk overwrites
        if (i < N_DST) {
            int ex = carry + incl - v;
            g_off[i]    = ex;
            g_cursor[i] = ex;
        }
        carry += total;
    }
    if (t == 0) g_off[N_DST] = carry;
}

__global__ void fill_kernel(const int* __restrict__ dst_idx) {
    int e = blockIdx.x * blockDim.x + threadIdx.x;
    if (e < NE) {
        int p = atomicAdd(&g_cursor[dst_idx[e]], 1);
        g_edges[p] = e;
    }
}

// ---------------------------------------------------------------------------
// SGEMM: C[M,128] = A[M,128] @ W[128,128]  (+ optional gather-add of g_ps)
// MODE 0: -> g_ps   MODE 1: -> g_nh   MODE 2: gather ps[src_idx[row]] -> g_m
// Tile 128x128, BK=16, 256 threads, 8x8 per thread.
// ---------------------------------------------------------------------------
template <int MODE>
__global__ __launch_bounds__(256, 2)
void sgemm128_kernel(const float* __restrict__ A, const float* __restrict__ W,
                     int M, const int* __restrict__ gidx)
{
    float* __restrict__ C = (MODE == 0) ? g_ps : (MODE == 1) ? g_nh : g_m;

    __shared__ float As[16][132];   // transposed A tile (k-major), padded
    __shared__ float Bs[16][128];

    const int tid = threadIdx.x;
    const int tx = tid & 15;        // output column group (8 cols)
    const int ty = tid >> 4;        // output row group (8 rows)
    const int row0 = blockIdx.x * 128;

    float acc[8][8];
    #pragma unroll
    for (int i = 0; i < 8; i++)
        #pragma unroll
        for (int j = 0; j < 8; j++) acc[i][j] = 0.f;

    for (int k0 = 0; k0 < 128; k0 += 16) {
        // Load A tile: 128 rows x 16 cols. 512 float4 slots, 2 per thread.
        #pragma unroll
        for (int i = 0; i < 2; i++) {
            int s  = tid * 2 + i;          // 0..511
            int r  = s >> 2;               // row in tile (4 float4 per row)
            int cc = (s & 3) * 4;          // col within the 16-wide K slab
            int gr = row0 + r;
            if (gr >= M) gr = M - 1;       // safe clamp; store is guarded later
            float4 v = *(const float4*)&A[(size_t)gr * FIN + k0 + cc];
            As[cc + 0][r] = v.x;
            As[cc + 1][r] = v.y;
            As[cc + 2][r] = v.z;
            As[cc + 3][r] = v.w;
        }
        // Load B tile: 16 rows x 128 cols, contiguous.
        #pragma unroll
        for (int i = 0; i < 2; i++) {
            int s  = tid * 2 + i;          // 0..511
            int r  = s >> 5;               // 32 float4 per row
            int cc = (s & 31) * 4;
            *(float4*)&Bs[r][cc] = *(const float4*)&W[(size_t)(k0 + r) * FIN + cc];
        }
        __syncthreads();

        #pragma unroll
        for (int kk = 0; kk < 16; kk++) {
            float a[8], b[8];
            *(float4*)&a[0] = *(const float4*)&As[kk][ty * 8];
            *(float4*)&a[4] = *(const float4*)&As[kk][ty * 8 + 4];
            *(float4*)&b[0] = *(const float4*)&Bs[kk][tx * 8];
            *(float4*)&b[4] = *(const float4*)&Bs[kk][tx * 8 + 4];
            #pragma unroll
            for (int i = 0; i < 8; i++)
                #pragma unroll
                for (int j = 0; j < 8; j++)
                    acc[i][j] += a[i] * b[j];
        }
        __syncthreads();
    }

    // Epilogue: optional gather-add, then store.
    #pragma unroll
    for (int i = 0; i < 8; i++) {
        int r  = ty * 8 + i;
        int gr = row0 + r;
        if (gr >= M) continue;
        float o[8];
        #pragma unroll
        for (int j = 0; j < 8; j++) o[j] = acc[i][j];
        if (MODE == 2) {
            int sn = gidx[gr];
            float4 p0 = *(const float4*)&g_ps[(size_t)sn * FIN + tx * 8];
            float4 p1 = *(const float4*)&g_ps[(size_t)sn * FIN + tx * 8 + 4];
            o[0] += p0.x; o[1] += p0.y; o[2] += p0.z; o[3] += p0.w;
            o[4] += p1.x; o[5] += p1.y; o[6] += p1.z; o[7] += p1.w;
        }
        *(float4*)&C[(size_t)gr * FIN + tx * 8]     = make_float4(o[0], o[1], o[2], o[3]);
        *(float4*)&C[(size_t)gr * FIN + tx * 8 + 4] = make_float4(o[4], o[5], o[6], o[7]);
    }
}

// ---------------------------------------------------------------------------
// Gather-reduce aggregation: one warp per destination node.
// Softmax without max-subtraction (mathematically identical; no overflow here:
// scores ~ N(0, ~2), |s|_max ~ 12 over 102M samples, exp fits fp32 easily).
// out[d,c] = sum_e m*exp(lrelu(m+nh)) / sum_e exp(lrelu(m+nh)) + bias
// ---------------------------------------------------------------------------
__device__ __forceinline__ float lrelu(float x) {
    return x > 0.f ? x : NEG_SLOPE * x;
}

__global__ void aggregate_kernel(const float* __restrict__ bias,
                                 float* __restrict__ out)
{
    int warp = (blockIdx.x * blockDim.x + threadIdx.x) >> 5;
    int lane = threadIdx.x & 31;
    if (warp >= N_DST) return;
    const int d = warp;

    float4 nh = ((const float4*)g_nh)[(size_t)d * 32 + lane];

    float4 num = make_float4(0.f, 0.f, 0.f, 0.f);
    float4 den = make_float4(0.f, 0.f, 0.f, 0.f);

    const int beg = g_off[d];
    const int end = g_off[d + 1];
    for (int j = beg; j < end; j++) {
        int e = g_edges[j];
        float4 m = ((const float4*)g_m)[(size_t)e * 32 + lane];
        float ex;
        ex = __expf(lrelu(m.x + nh.x)); num.x += m.x * ex; den.x += ex;
        ex = __expf(lrelu(m.y + nh.y)); num.y += m.y * ex; den.y += ex;
        ex = __expf(lrelu(m.z + nh.z)); num.z += m.z * ex; den.z += ex;
        ex = __expf(lrelu(m.w + nh.w)); num.w += m.w * ex; den.w += ex;
    }

    float4 b4 = ((const float4*)bias)[lane];
    float4 o;
    o.x = (den.x > 0.f) ? num.x / den.x + b4.x : b4.x;
    o.y = (den.y > 0.f) ? num.y / den.y + b4.y : b4.y;
    o.z = (den.z > 0.f) ? num.z / den.z + b4.z : b4.z;
    o.w = (den.w > 0.f) ? num.w / den.w + b4.w : b4.w;
    ((float4*)out)[(size_t)d * 32 + lane] = o;
}

// ---------------------------------------------------------------------------
// Launch
// ---------------------------------------------------------------------------
extern "C" void kernel_launch(void* const* d_in, const int* in_sizes, int n_in,
                              void* d_out, int out_size)
{
    const float* src_feat  = (const float*)d_in[0];
    const float* dst_feat  = (const float*)d_in[1];
    const float* edge_feat = (const float*)d_in[2];
    const float* W_src     = (const float*)d_in[3];   // [256,128] row-major
    const float* W_dst     = (const float*)d_in[4];   // [128,128]
    const float* bias      = (const float*)d_in[5];   // [128]
    const int*   src_idx   = (const int*)d_in[6];
    const int*   dst_idx   = (const int*)d_in[7];
    float* out = (float*)d_out;

    const float* W_top  = W_src;                 // rows 0..127  (src part)
    const float* W_edge = W_src + 128 * FIN;     // rows 128..255 (edge part)

    // CSR build
    zero_deg_kernel<<<(N_DST + 255) / 256, 256>>>();
    hist_kernel<<<(NE + 255) / 256, 256>>>(dst_idx);
    scan_kernel<<<1, 1024>>>();
    fill_kernel<<<(NE + 255) / 256, 256>>>(dst_idx);

    // Node projections
    sgemm128_kernel<0><<<(N_SRC + 127) / 128, 256>>>(src_feat, W_top,  N_SRC, nullptr);
    sgemm128_kernel<1><<<(N_DST + 127) / 128, 256>>>(dst_feat, W_dst,  N_DST, nullptr);

    // Edge messages: m = edge_feat @ W_edge + ps[src_idx]   (dominant GEMM)
    sgemm128_kernel<2><<<NE / 128, 256>>>(edge_feat, W_edge, NE, src_idx);

    // Segment softmax + weighted aggregation (gather-reduce, no atomics)
    aggregate_kernel<<<(N_DST * 32 + 255) / 256, 256>>>(bias, out);
}

// round 6
// speedup vs baseline: 1.0685x; 1.0685x over previous
#include <cuda_runtime.h>
#include <cuda_bf16.h>
#include <cstdint>

#define N_SRC 50000
#define N_DST 50000
#define NE    800000
#define FIN   128
#define NEG_SLOPE 0.2f

// ---------------------------------------------------------------------------
// Scratch (__device__ globals; no runtime allocation allowed)
// ---------------------------------------------------------------------------
__device__ float g_m[(size_t)NE * FIN];     // per-edge messages, CSR-sorted order
__device__ float g_ps[(size_t)N_SRC * FIN]; // src_feat @ W_src[:128]
__device__ float g_nh[(size_t)N_DST * FIN]; // dst_feat @ W_dst
__device__ int   g_deg[N_DST];
__device__ int   g_off[N_DST + 1];
__device__ int   g_cursor[N_DST];
__device__ int   g_edges[NE];               // edge ids grouped by dst (CSR)

// ---------------------------------------------------------------------------
// CSR build
// ---------------------------------------------------------------------------
__global__ void zero_deg_kernel() {
    int i = blockIdx.x * blockDim.x + threadIdx.x;
    if (i < N_DST) g_deg[i] = 0;
}
__global__ void hist_kernel(const int* __restrict__ dst_idx) {
    int e = blockIdx.x * blockDim.x + threadIdx.x;
    if (e < NE) atomicAdd(&g_deg[dst_idx[e]], 1);
}
__global__ void scan_kernel() {
    __shared__ int sh[1024];
    const int t = threadIdx.x;
    int carry = 0;
    for (int base = 0; base < N_DST; base += 1024) {
        int i = base + t;
        int v = (i < N_DST) ? g_deg[i] : 0;
        sh[t] = v;
        __syncthreads();
        #pragma unroll
        for (int off = 1; off < 1024; off <<= 1) {
            int tmp = (t >= off) ? sh[t - off] : 0;
            __syncthreads();
            sh[t] += tmp;
            __syncthreads();
        }
        int incl = sh[t];
        int total = sh[1023];
        __syncthreads();
        if (i < N_DST) {
            int ex = carry + incl - v;
            g_off[i] = ex;
            g_cursor[i] = ex;
        }
        carry += total;
    }
    if (t == 0) g_off[N_DST] = carry;
}
__global__ void fill_kernel(const int* __restrict__ dst_idx) {
    int e = blockIdx.x * blockDim.x + threadIdx.x;
    if (e < NE) {
        int p = atomicAdd(&g_cursor[dst_idx[e]], 1);
        g_edges[p] = e;
    }
}

// ---------------------------------------------------------------------------
// Warp-level bf16 MMA (base ISA, sm_80+; compiles on compute_103)
// m16n8k16, A row-major, B col-major, fp32 accumulate
// ---------------------------------------------------------------------------
__device__ __forceinline__ void mma_bf16(float* c, const uint32_t* a, const uint32_t* b) {
    asm volatile(
        "mma.sync.aligned.m16n8k16.row.col.f32.bf16.bf16.f32 "
        "{%0,%1,%2,%3}, {%4,%5,%6,%7}, {%8,%9}, {%0,%1,%2,%3};\n"
        : "+f"(c[0]), "+f"(c[1]), "+f"(c[2]), "+f"(c[3])
        : "r"(a[0]), "r"(a[1]), "r"(a[2]), "r"(a[3]),
          "r"(b[0]), "r"(b[1]));
}

// ---------------------------------------------------------------------------
// SMEM layout: padded bf16 tiles, stride 136 halves (272 B) -> conflict-free
//   Ah[128][136] | Al[128][136] | Bh[128][136] | Bl[128][136] | s_src[128]
// B tile stored as [n][k] (k contiguous) = col-major k x n for the MMA.
// ---------------------------------------------------------------------------
#define ASTRIDE 136
#define TILE_HALFS (128 * ASTRIDE)               // 17408 halves = 34816 B
#define OFF_AH 0
#define OFF_AL (TILE_HALFS)
#define OFF_BH (2 * TILE_HALFS)
#define OFF_BL (3 * TILE_HALFS)
#define SMEM_HALFS (4 * TILE_HALFS)
#define SMEM_TOTAL (SMEM_HALFS * 2 + 128 * 4)    // + s_src ints

// ---------------------------------------------------------------------------
// Persistent GEMM: C[M,128] = A[M,128] @ W[128,128]
// MODE 0: A rows plain -> g_ps
// MODE 1: A rows plain -> g_nh
// MODE 2: A row r = edge_feat[g_edges[r]]; C += g_ps[src_idx[edge]]; -> g_m
// 2-term bf16 split, 3 chains (ah*bh + ah*bl + al*bh) into one fp32 accum.
// 8 warps: warp tile 32 (rows) x 64 (cols).
// ---------------------------------------------------------------------------
template <int MODE>
__global__ __launch_bounds__(256, 1)
void gat_gemm(const float* __restrict__ A, const float* __restrict__ W,
              int M, const int* __restrict__ src_idx)
{
    extern __shared__ __nv_bfloat16 smh[];
    int* s_src = (int*)(smh + SMEM_HALFS);

    const int tid  = threadIdx.x;
    const int wid  = tid >> 5;
    const int lane = tid & 31;
    const int g    = lane >> 2;          // fragment group row
    const int tg   = lane & 3;           // thread-in-group
    const int wm   = wid & 3;            // warp row group (x32 rows)
    const int wn   = wid >> 2;           // warp col group (x64 cols)
    const int r0w  = wm * 32;
    const int c0w  = wn * 64;

    // ---- Convert B once: Bs[n][k] = W[k][n], hi/lo split -------------------
    for (int s = tid; s < 128 * 32; s += 256) {
        int k  = s >> 5;
        int n0 = (s & 31) << 2;
        float4 v = *(const float4*)&W[k * FIN + n0];
        float vv[4] = {v.x, v.y, v.z, v.w};
        #pragma unroll
        for (int j = 0; j < 4; j++) {
            __nv_bfloat16 h = __float2bfloat16_rn(vv[j]);
            __nv_bfloat16 l = __float2bfloat16_rn(vv[j] - __bfloat162float(h));
            smh[OFF_BH + (n0 + j) * ASTRIDE + k] = h;
            smh[OFF_BL + (n0 + j) * ASTRIDE + k] = l;
        }
    }
    __syncthreads();

    const int ntiles = (M + 127) >> 7;

    for (int t = blockIdx.x; t < ntiles; t += gridDim.x) {
        const int row0 = t << 7;

        // ---- Load + split-convert A tile ----------------------------------
        #pragma unroll 4
        for (int i = 0; i < 16; i++) {
            int s = tid + i * 256;          // 0..4095 float4 slots
            int r = s >> 5;
            int c = (s & 31) << 2;
            int gr = row0 + r;
            int ar;
            if (MODE == 2) ar = g_edges[gr];
            else           ar = (gr < M) ? gr : (M - 1);
            float4 v = *(const float4*)&A[(size_t)ar * FIN + c];
            float vv[4] = {v.x, v.y, v.z, v.w};
            uint32_t hw[2], lw[2];
            #pragma unroll
            for (int j = 0; j < 2; j++) {
                __nv_bfloat16 h0 = __float2bfloat16_rn(vv[j * 2]);
                __nv_bfloat16 h1 = __float2bfloat16_rn(vv[j * 2 + 1]);
                __nv_bfloat16 l0 = __float2bfloat16_rn(vv[j * 2]     - __bfloat162float(h0));
                __nv_bfloat16 l1 = __float2bfloat16_rn(vv[j * 2 + 1] - __bfloat162float(h1));
                hw[j] = (uint32_t)__bfloat16_as_ushort(h0) | ((uint32_t)__bfloat16_as_ushort(h1) << 16);
                lw[j] = (uint32_t)__bfloat16_as_ushort(l0) | ((uint32_t)__bfloat16_as_ushort(l1) << 16);
            }
            *(uint2*)&smh[OFF_AH + r * ASTRIDE + c] = make_uint2(hw[0], hw[1]);
            *(uint2*)&smh[OFF_AL + r * ASTRIDE + c] = make_uint2(lw[0], lw[1]);
            if (MODE == 2 && (s & 31) == 0) s_src[r] = src_idx[ar];
        }
        __syncthreads();

        // ---- Compute: 8 k-steps, 48 mma each ------------------------------
        float acc[2][8][4];
        #pragma unroll
        for (int mi = 0; mi < 2; mi++)
            #pragma unroll
            for (int ni = 0; ni < 8; ni++)
                #pragma unroll
                for (int q = 0; q < 4; q++) acc[mi][ni][q] = 0.f;

        for (int ks = 0; ks < 8; ks++) {
            const int k0 = ks * 16;
            const int kc = k0 + tg * 2;

            uint32_t ah[2][4], al[2][4];
            #pragma unroll
            for (int mi = 0; mi < 2; mi++) {
                int rbase = (r0w + mi * 16 + g) * ASTRIDE + kc;
                ah[mi][0] = *(const uint32_t*)&smh[OFF_AH + rbase];
                ah[mi][1] = *(const uint32_t*)&smh[OFF_AH + rbase + 8 * ASTRIDE];
                ah[mi][2] = *(const uint32_t*)&smh[OFF_AH + rbase + 8];
                ah[mi][3] = *(const uint32_t*)&smh[OFF_AH + rbase + 8 * ASTRIDE + 8];
                al[mi][0] = *(const uint32_t*)&smh[OFF_AL + rbase];
                al[mi][1] = *(const uint32_t*)&smh[OFF_AL + rbase + 8 * ASTRIDE];
                al[mi][2] = *(const uint32_t*)&smh[OFF_AL + rbase + 8];
                al[mi][3] = *(const uint32_t*)&smh[OFF_AL + rbase + 8 * ASTRIDE + 8];
            }
            uint32_t bh[8][2], bl[8][2];
            #pragma unroll
            for (int ni = 0; ni < 8; ni++) {
                int nbase = (c0w + ni * 8 + g) * ASTRIDE + kc;
                bh[ni][0] = *(const uint32_t*)&smh[OFF_BH + nbase];
                bh[ni][1] = *(const uint32_t*)&smh[OFF_BH + nbase + 8];
                bl[ni][0] = *(const uint32_t*)&smh[OFF_BL + nbase];
                bl[ni][1] = *(const uint32_t*)&smh[OFF_BL + nbase + 8];
            }
            #pragma unroll
            for (int mi = 0; mi < 2; mi++)
                #pragma unroll
                for (int ni = 0; ni < 8; ni++) {
                    mma_bf16(acc[mi][ni], ah[mi], bh[ni]);  // hi*hi
                    mma_bf16(acc[mi][ni], ah[mi], bl[ni]);  // hi*lo
                    mma_bf16(acc[mi][ni], al[mi], bh[ni]);  // lo*hi
                }
        }

        // ---- Epilogue: fragment stores (+ ps gather-add for MODE 2) -------
        {
            float* __restrict__ C = (MODE == 0) ? g_ps : (MODE == 1) ? g_nh : g_m;
            #pragma unroll
            for (int mi = 0; mi < 2; mi++) {
                int ra  = r0w + mi * 16 + g;
                int rb  = ra + 8;
                int gra = row0 + ra;
                int grb = row0 + rb;
                int sa = 0, sb = 0;
                if (MODE == 2) { sa = s_src[ra]; sb = s_src[rb]; }
                bool oka = (MODE == 2) || (gra < M);
                bool okb = (MODE == 2) || (grb < M);
                #pragma unroll
                for (int ni = 0; ni < 8; ni++) {
                    int col = c0w + ni * 8 + tg * 2;
                    float2 v0 = make_float2(acc[mi][ni][0], acc[mi][ni][1]);
                    float2 v1 = make_float2(acc[mi][ni][2], acc[mi][ni][3]);
                    if (MODE == 2) {
                        float2 p0 = *(const float2*)&g_ps[(size_t)sa * FIN + col];
                        float2 p1 = *(const float2*)&g_ps[(size_t)sb * FIN + col];
                        v0.x += p0.x; v0.y += p0.y;
                        v1.x += p1.x; v1.y += p1.y;
                    }
                    if (oka) *(float2*)&C[(size_t)gra * FIN + col] = v0;
                    if (okb) *(float2*)&C[(size_t)grb * FIN + col] = v1;
                }
            }
        }
        __syncthreads();   // A tile / s_src reuse barrier
    }
}

// ---------------------------------------------------------------------------
// Aggregation: one warp per destination; g_m is CSR-contiguous.
// Softmax without max-subtraction (scores ~N(0,2); exp safe in fp32).
// ---------------------------------------------------------------------------
__device__ __forceinline__ float lrelu(float x) { return x > 0.f ? x : NEG_SLOPE * x; }

__global__ void aggregate_kernel(const float* __restrict__ bias, float* __restrict__ out)
{
    int warp = (blockIdx.x * blockDim.x + threadIdx.x) >> 5;
    int lane = threadIdx.x & 31;
    if (warp >= N_DST) return;
    const int d = warp;

    float4 nh = ((const float4*)g_nh)[(size_t)d * 32 + lane];
    float4 num = make_float4(0.f, 0.f, 0.f, 0.f);
    float4 den = make_float4(0.f, 0.f, 0.f, 0.f);

    const int beg = g_off[d];
    const int end = g_off[d + 1];
    for (int j = beg; j < end; j++) {
        float4 m = ((const float4*)g_m)[(size_t)j * 32 + lane];
        float ex;
        ex = __expf(lrelu(m.x + nh.x)); num.x += m.x * ex; den.x += ex;
        ex = __expf(lrelu(m.y + nh.y)); num.y += m.y * ex; den.y += ex;
        ex = __expf(lrelu(m.z + nh.z)); num.z += m.z * ex; den.z += ex;
        ex = __expf(lrelu(m.w + nh.w)); num.w += m.w * ex; den.w += ex;
    }

    float4 b4 = ((const float4*)bias)[lane];
    float4 o;
    o.x = (den.x > 0.f) ? num.x / den.x + b4.x : b4.x;
    o.y = (den.y > 0.f) ? num.y / den.y + b4.y : b4.y;
    o.z = (den.z > 0.f) ? num.z / den.z + b4.z : b4.z;
    o.w = (den.w > 0.f) ? num.w / den.w + b4.w : b4.w;
    ((float4*)out)[(size_t)d * 32 + lane] = o;
}

// ---------------------------------------------------------------------------
// Launch
// ---------------------------------------------------------------------------
extern "C" void kernel_launch(void* const* d_in, const int* in_sizes, int n_in,
                              void* d_out, int out_size)
{
    const float* src_feat  = (const float*)d_in[0];
    const float* dst_feat  = (const float*)d_in[1];
    const float* edge_feat = (const float*)d_in[2];
    const float* W_src     = (const float*)d_in[3];   // [256,128]
    const float* W_dst     = (const float*)d_in[4];   // [128,128]
    const float* bias      = (const float*)d_in[5];   // [128]
    const int*   src_idx   = (const int*)d_in[6];
    const int*   dst_idx   = (const int*)d_in[7];
    float* out = (float*)d_out;

    const float* W_top  = W_src;              // rows 0..127  (src part)
    const float* W_edge = W_src + 128 * FIN;  // rows 128..255 (edge part)

    cudaFuncSetAttribute(gat_gemm<0>, cudaFuncAttributeMaxDynamicSharedMemorySize, SMEM_TOTAL);
    cudaFuncSetAttribute(gat_gemm<1>, cudaFuncAttributeMaxDynamicSharedMemorySize, SMEM_TOTAL);
    cudaFuncSetAttribute(gat_gemm<2>, cudaFuncAttributeMaxDynamicSharedMemorySize, SMEM_TOTAL);

    // CSR build (needed by edge GEMM for CSR-ordered writes)
    zero_deg_kernel<<<(N_DST + 255) / 256, 256>>>();
    hist_kernel<<<(NE + 255) / 256, 256>>>(dst_idx);
    scan_kernel<<<1, 1024>>>();
    fill_kernel<<<(NE + 255) / 256, 256>>>(dst_idx);

    const int NBLK = 148;   // persistent: ~1 CTA per SM

    // Node projections
    gat_gemm<0><<<NBLK, 256, SMEM_TOTAL>>>(src_feat, W_top, N_SRC, nullptr);
    gat_gemm<1><<<NBLK, 256, SMEM_TOTAL>>>(dst_feat, W_dst, N_DST, nullptr);

    // Edge messages in CSR order: m[j] = edge_feat[g_edges[j]] @ W_edge + ps[src_idx[g_edges[j]]]
    gat_gemm<2><<<NBLK, 256, SMEM_TOTAL>>>(edge_feat, W_edge, NE, src_idx);

    // Segment softmax + weighted aggregation (fully sequential g_m reads)
    aggregate_kernel<<<(N_DST * 32 + 255) / 256, 256>>>(bias, out);
}